// round 13
// baseline (speedup 1.0000x reference)
#include <cuda_runtime.h>
#include <cfloat>
#include <cstdint>

// Problem constants (fixed shapes from reference)
#define PB   2
#define PH   4
#define PLQ  512
#define PLKV 512
#define PD   64
#define PBH  (PB * PH)     // 8
#define TQ   4             // q-rows per block (R9 lesson: TQ=8 needs >=150 regs)

// Scratch for projected q/k (allocation-free rule: __device__ globals)
__device__ __align__(16) float g_qp[PBH * PLQ * PD];   // qp + b_concat folded in
__device__ __align__(16) float g_kp[PBH * PLKV * PD];

__device__ __forceinline__ float tanh_fast(float x) {
    float r;
    asm("tanh.approx.f32 %0, %1;" : "=f"(r) : "f"(x));
    return r;
}

// ---------------------------------------------------------------------------
// Projection, tiled: 64 rows per block, W-half staged in smem (coalesced).
// (Measured good: proj+overhead small. Unchanged.)
// ---------------------------------------------------------------------------
__global__ __launch_bounds__(256) void proj_kernel(
    const float* __restrict__ Q, const float* __restrict__ K,
    const float* __restrict__ W, const float* __restrict__ bias)
{
    __shared__ __align__(16) float sW[PD][68];
    __shared__ __align__(16) float sIn[64][68];

    const int tid = threadIdx.x;
    const int r0  = blockIdx.x * 64;               // global row among 2*BH*LQ
    const bool isQ = (r0 < PBH * PLQ);
    const int rr0  = isQ ? r0 : (r0 - PBH * PLQ);
    const float* in = (isQ ? Q : K) + (size_t)rr0 * PD;
    const int woff = isQ ? 0 : PD;

    // Stage 64 input rows (coalesced float4)
    for (int i = tid; i < 64 * (PD / 4); i += 256) {
        int r = i >> 4, d4 = i & 15;
        float4 v = ((const float4*)(in + (size_t)r * PD))[d4];
        *(float4*)&sIn[r][d4 * 4] = v;
    }
    // Stage W half (e-major rows)
    for (int i = tid; i < PD * (PD / 4); i += 256) {
        int e = i >> 4, d4 = i & 15;
        float4 v = *(const float4*)(W + (size_t)e * (2 * PD) + woff + d4 * 4);
        *(float4*)&sW[e][d4 * 4] = v;
    }
    __syncthreads();

    const int e  = tid & 63;
    const int rg = tid >> 6;       // 4 groups x 16 rows
    const float b = isQ ? bias[e] : 0.0f;

    float acc[16];
#pragma unroll
    for (int r = 0; r < 16; r++) acc[r] = b;

#pragma unroll
    for (int d4 = 0; d4 < PD / 4; d4++) {
        float4 wv = *(const float4*)&sW[e][d4 * 4];
#pragma unroll
        for (int r = 0; r < 16; r++) {
            float4 iv = *(const float4*)&sIn[rg * 16 + r][d4 * 4]; // broadcast
            acc[r] += wv.x * iv.x + wv.y * iv.y + wv.z * iv.z + wv.w * iv.w;
        }
    }

    float* dst = (isQ ? g_qp : g_kp) + (size_t)rr0 * PD;
#pragma unroll
    for (int r = 0; r < 16; r++)
        dst[(size_t)(rg * 16 + r) * PD + e] = acc[r];   // coalesced STG.32
}

// ---------------------------------------------------------------------------
// Main kernel: one block = (bh, 4 consecutive q rows), all 512 k.
//   R12 lesson: UNCAPPED, ptxas pipelines until it eats 255 regs -> stuck at
//   2 warps/SMSP regardless of TQ (R5=168, R12=255, both issue ~20%).
//   R9 lesson: cap below natural demand -> spills (TQ=8 demand >128).
//   This round: TQ=4 (demand ~90-115) + cap 128 via (128,4):
//   spill-free fit AND 4 CTAs/SM = 16 warps = 4/SMSP.
//   Phase 1: logits[q][k] = sum_e w[e]*tanh(qp[q,e] + kp[k,e])
//   Phase 2: per-warp masked softmax (4 warps = 4 q rows), write weights.
// Grid: BH * (LQ/TQ) = 1024 blocks, 128 threads.
// ---------------------------------------------------------------------------
__global__ __launch_bounds__(128, 4) void attn_kernel(
    const int* __restrict__ mask,
    const float* __restrict__ w_logit,
    float* __restrict__ out)
{
    __shared__ __align__(16) float qp_s[TQ][PD];   // 1 KB
    __shared__ __align__(16) float ws[PD];         // 256 B
    __shared__ float logits_s[TQ][PLKV];           // 8 KB

    const int bh  = blockIdx.x / (PLQ / TQ);
    const int qt  = blockIdx.x % (PLQ / TQ);
    const int q0  = qt * TQ;
    const int tid = threadIdx.x;

    // Load qp tile (TQ*D = 256 floats) and w_logit into shared
    const float* qpbase = g_qp + ((size_t)bh * PLQ + q0) * PD;
    for (int i = tid; i < TQ * PD; i += 128)
        ((float*)qp_s)[i] = qpbase[i];
    if (tid < PD) ws[tid] = w_logit[tid];
    __syncthreads();

    const float*  kpbase = g_kp + (size_t)bh * PLKV * PD;
    const float4* ws4    = (const float4*)ws;

    // ---- Phase 1: logits ----
    for (int c = 0; c < PLKV; c += 128) {
        const int k = c + tid;
        const float4* kp4 = (const float4*)(kpbase + (size_t)k * PD);

        float acc[TQ];
#pragma unroll
        for (int q = 0; q < TQ; q++) acc[q] = 0.0f;

#pragma unroll
        for (int quarter = 0; quarter < 4; quarter++) {
            float4 ka[4];                       // 16 e-values of kp
#pragma unroll
            for (int i = 0; i < 4; i++) ka[i] = kp4[quarter * 4 + i]; // batched LDG

#pragma unroll
            for (int q = 0; q < TQ; q++) {
                const float4* qp4 = (const float4*)qp_s[q];
                float a0 = 0.0f, a1 = 0.0f;
#pragma unroll
                for (int e4 = 0; e4 < 4; e4++) {
                    float4 qv = qp4[quarter * 4 + e4];   // broadcast LDS.128
                    float4 wv = ws4[quarter * 4 + e4];   // broadcast LDS.128
                    a0 += wv.x * tanh_fast(qv.x + ka[e4].x);
                    a1 += wv.y * tanh_fast(qv.y + ka[e4].y);
                    a0 += wv.z * tanh_fast(qv.z + ka[e4].z);
                    a1 += wv.w * tanh_fast(qv.w + ka[e4].w);
                }
                acc[q] += a0 + a1;
            }
        }
#pragma unroll
        for (int q = 0; q < TQ; q++)
            logits_s[q][k] = acc[q];
    }
    __syncthreads();

    // ---- Phase 2: masked softmax, one warp per q row (4 warps) ----
    const int w    = tid >> 5;
    const int lane = tid & 31;
    const int qg   = q0 + w;
    const int b    = bh / PH;
    const int* mrow = mask + ((size_t)b * PLQ + qg) * PLKV;

    float m_val = -FLT_MAX, m_raw = -FLT_MAX;
    int anyv = 0;
    for (int j = lane; j < PLKV; j += 32) {
        float l = logits_s[w][j];
        int   v = mrow[j] != 0;
        anyv |= v;
        m_raw = fmaxf(m_raw, l);
        if (v) m_val = fmaxf(m_val, l);
    }
#pragma unroll
    for (int o = 16; o; o >>= 1) {
        m_val = fmaxf(m_val, __shfl_xor_sync(0xffffffffu, m_val, o));
        m_raw = fmaxf(m_raw, __shfl_xor_sync(0xffffffffu, m_raw, o));
    }
    const bool any = __ballot_sync(0xffffffffu, anyv) != 0;
    const float M = any ? m_val : m_raw;

    float s = 0.0f;
    for (int j = lane; j < PLKV; j += 32) {
        float l = logits_s[w][j];
        bool  v = (!any) || (mrow[j] != 0);
        float p = v ? __expf(l - M) : 0.0f;
        logits_s[w][j] = p;
        s += p;
    }
#pragma unroll
    for (int o = 16; o; o >>= 1)
        s += __shfl_xor_sync(0xffffffffu, s, o);
    const float inv = 1.0f / s;

    float* orow = out + ((size_t)bh * PLQ + qg) * PLKV;
    for (int j = lane; j < PLKV; j += 32)
        orow[j] = logits_s[w][j] * inv;
}

// ---------------------------------------------------------------------------
// Inputs (metadata order): queries, keys, values(unused), mask(int32),
// W_concat, b_concat, w_logit, b_logit(unused: softmax shift-invariant)
// ---------------------------------------------------------------------------
extern "C" void kernel_launch(void* const* d_in, const int* in_sizes, int n_in,
                              void* d_out, int out_size)
{
    const float* Q    = (const float*)d_in[0];
    const float* K    = (const float*)d_in[1];
    const int*   mask = (const int*)d_in[3];
    const float* W    = (const float*)d_in[4];
    const float* bc   = (const float*)d_in[5];
    const float* wl   = (const float*)d_in[6];
    float*       out  = (float*)d_out;

    proj_kernel<<<(2 * PBH * PLQ) / 64, 256>>>(Q, K, W, bc);
    attn_kernel<<<PBH * (PLQ / TQ), 128>>>(mask, wl, out);
}

// round 14
// speedup vs baseline: 2.3053x; 2.3053x over previous
#include <cuda_runtime.h>
#include <cfloat>
#include <cstdint>

// Problem constants (fixed shapes from reference)
#define PB   2
#define PH   4
#define PLQ  512
#define PLKV 512
#define PD   64
#define PBH  (PB * PH)     // 8
#define TQ   8             // q-rows per block
#define KT   128           // k-tile rows staged in smem

// Scratch for projected q/k (allocation-free rule: __device__ globals)
__device__ __align__(16) float g_qp[PBH * PLQ * PD];   // qp + b_concat folded in
__device__ __align__(16) float g_kp[PBH * PLKV * PD];

__device__ __forceinline__ float tanh_fast(float x) {
    float r;
    asm("tanh.approx.f32 %0, %1;" : "=f"(r) : "f"(x));
    return r;
}

// ---------------------------------------------------------------------------
// Projection, tiled: 64 rows per block, W-half staged in smem (coalesced).
// (Measured good. Unchanged.)
// ---------------------------------------------------------------------------
__global__ __launch_bounds__(256) void proj_kernel(
    const float* __restrict__ Q, const float* __restrict__ K,
    const float* __restrict__ W, const float* __restrict__ bias)
{
    __shared__ __align__(16) float sW[PD][68];
    __shared__ __align__(16) float sIn[64][68];

    const int tid = threadIdx.x;
    const int r0  = blockIdx.x * 64;               // global row among 2*BH*LQ
    const bool isQ = (r0 < PBH * PLQ);
    const int rr0  = isQ ? r0 : (r0 - PBH * PLQ);
    const float* in = (isQ ? Q : K) + (size_t)rr0 * PD;
    const int woff = isQ ? 0 : PD;

    for (int i = tid; i < 64 * (PD / 4); i += 256) {
        int r = i >> 4, d4 = i & 15;
        float4 v = ((const float4*)(in + (size_t)r * PD))[d4];
        *(float4*)&sIn[r][d4 * 4] = v;
    }
    for (int i = tid; i < PD * (PD / 4); i += 256) {
        int e = i >> 4, d4 = i & 15;
        float4 v = *(const float4*)(W + (size_t)e * (2 * PD) + woff + d4 * 4);
        *(float4*)&sW[e][d4 * 4] = v;
    }
    __syncthreads();

    const int e  = tid & 63;
    const int rg = tid >> 6;       // 4 groups x 16 rows
    const float b = isQ ? bias[e] : 0.0f;

    float acc[16];
#pragma unroll
    for (int r = 0; r < 16; r++) acc[r] = b;

#pragma unroll
    for (int d4 = 0; d4 < PD / 4; d4++) {
        float4 wv = *(const float4*)&sW[e][d4 * 4];
#pragma unroll
        for (int r = 0; r < 16; r++) {
            float4 iv = *(const float4*)&sIn[rg * 16 + r][d4 * 4]; // broadcast
            acc[r] += wv.x * iv.x + wv.y * iv.y + wv.z * iv.z + wv.w * iv.w;
        }
    }

    float* dst = (isQ ? g_qp : g_kp) + (size_t)rr0 * PD;
#pragma unroll
    for (int r = 0; r < 16; r++)
        dst[(size_t)(rg * 16 + r) * PD + e] = acc[r];   // coalesced STG.32
}

// ---------------------------------------------------------------------------
// Main kernel: one block = (bh, 8 q rows), k processed in 4 smem-staged tiles.
//   R13 lesson: per-thread LDG of kp rows needs ~250-cyc L2 latency hiding ->
//   ptxas burns 168-255 regs on prefetch; capping causes spills/stalls.
//   Fix: cooperative coalesced tile load kp[KT][PD] -> smem (stride 68,
//   conflict-free LDS.128), inner loop touches ONLY LDS (29 cyc). Per-thread
//   state ~= acc[8]+ka[4]+temps -> cap (128,4) is spill-free: 4 CTAs/SM
//   = 16 warps = 4/SMSP, cross-CTA overlap hides tile-load phases.
//   Phase 2: 4 warps x 2 q rows masked softmax.
// Grid: BH * (LQ/TQ) = 512 blocks, 128 threads.
// ---------------------------------------------------------------------------
__global__ __launch_bounds__(128, 4) void attn_kernel(
    const int* __restrict__ mask,
    const float* __restrict__ w_logit,
    float* __restrict__ out)
{
    __shared__ __align__(16) float qp_s[TQ][PD];     // 2 KB
    __shared__ __align__(16) float ws[PD];           // 256 B
    __shared__ __align__(16) float kt_s[KT][68];     // 34 KB k-tile
    __shared__ float logits_s[TQ][PLKV];             // 16 KB

    const int bh  = blockIdx.x / (PLQ / TQ);
    const int qt  = blockIdx.x % (PLQ / TQ);
    const int q0  = qt * TQ;
    const int tid = threadIdx.x;

    // Load qp tile (TQ*D = 512 floats) and w_logit into shared
    const float* qpbase = g_qp + ((size_t)bh * PLQ + q0) * PD;
    for (int i = tid; i < TQ * PD; i += 128)
        ((float*)qp_s)[i] = qpbase[i];
    if (tid < PD) ws[tid] = w_logit[tid];

    const float*  kpbase = g_kp + (size_t)bh * PLKV * PD;
    const float4* ws4    = (const float4*)ws;

    // ---- Phase 1: logits, k in 4 tiles of KT=128 ----
    for (int t = 0; t < PLKV / KT; t++) {
        __syncthreads();   // protect kt_s reuse (also covers qp_s/ws on t=0)
        // Cooperative coalesced load: KT rows x 16 float4 = 2048 float4
        const float4* src = (const float4*)(kpbase + (size_t)t * KT * PD);
        for (int i = tid; i < KT * (PD / 4); i += 128) {
            int r = i >> 4, d4 = i & 15;
            *(float4*)&kt_s[r][d4 * 4] = src[i];
        }
        __syncthreads();

        const int k = t * KT + tid;               // tid < 128 = KT
        const float4* kp4 = (const float4*)kt_s[tid];

        float acc[TQ];
#pragma unroll
        for (int q = 0; q < TQ; q++) acc[q] = 0.0f;

#pragma unroll
        for (int quarter = 0; quarter < 4; quarter++) {
            float4 ka[4];                         // 16 e-values from smem
#pragma unroll
            for (int i = 0; i < 4; i++) ka[i] = kp4[quarter * 4 + i]; // LDS.128 stride-68: conflict-free

#pragma unroll
            for (int q = 0; q < TQ; q++) {
                const float4* qp4 = (const float4*)qp_s[q];
                float a0 = 0.0f, a1 = 0.0f;
#pragma unroll
                for (int e4 = 0; e4 < 4; e4++) {
                    float4 qv = qp4[quarter * 4 + e4];   // broadcast LDS.128
                    float4 wv = ws4[quarter * 4 + e4];   // broadcast LDS.128
                    a0 += wv.x * tanh_fast(qv.x + ka[e4].x);
                    a1 += wv.y * tanh_fast(qv.y + ka[e4].y);
                    a0 += wv.z * tanh_fast(qv.z + ka[e4].z);
                    a1 += wv.w * tanh_fast(qv.w + ka[e4].w);
                }
                acc[q] += a0 + a1;
            }
        }
#pragma unroll
        for (int q = 0; q < TQ; q++)
            logits_s[q][k] = acc[q];
    }
    __syncthreads();

    // ---- Phase 2: masked softmax, 4 warps x 2 q rows ----
    const int wid  = tid >> 5;
    const int lane = tid & 31;
    const int b    = bh / PH;

#pragma unroll
    for (int rep = 0; rep < 2; rep++) {
        const int w  = wid + rep * 4;             // q row within tile
        const int qg = q0 + w;
        const int* mrow = mask + ((size_t)b * PLQ + qg) * PLKV;

        float m_val = -FLT_MAX, m_raw = -FLT_MAX;
        int anyv = 0;
        for (int j = lane; j < PLKV; j += 32) {
            float l = logits_s[w][j];
            int   v = mrow[j] != 0;
            anyv |= v;
            m_raw = fmaxf(m_raw, l);
            if (v) m_val = fmaxf(m_val, l);
        }
#pragma unroll
        for (int o = 16; o; o >>= 1) {
            m_val = fmaxf(m_val, __shfl_xor_sync(0xffffffffu, m_val, o));
            m_raw = fmaxf(m_raw, __shfl_xor_sync(0xffffffffu, m_raw, o));
        }
        const bool any = __ballot_sync(0xffffffffu, anyv) != 0;
        const float M = any ? m_val : m_raw;

        float s = 0.0f;
        float pbuf[PLKV / 32];
#pragma unroll
        for (int jj = 0; jj < PLKV / 32; jj++) {
            int j = lane + jj * 32;
            float l = logits_s[w][j];
            bool  v = (!any) || (mrow[j] != 0);
            float p = v ? __expf(l - M) : 0.0f;
            pbuf[jj] = p;
            s += p;
        }
#pragma unroll
        for (int o = 16; o; o >>= 1)
            s += __shfl_xor_sync(0xffffffffu, s, o);
        const float inv = 1.0f / s;

        float* orow = out + ((size_t)bh * PLQ + qg) * PLKV;
#pragma unroll
        for (int jj = 0; jj < PLKV / 32; jj++)
            orow[lane + jj * 32] = pbuf[jj] * inv;
    }
}

// ---------------------------------------------------------------------------
// Inputs (metadata order): queries, keys, values(unused), mask(int32),
// W_concat, b_concat, w_logit, b_logit(unused: softmax shift-invariant)
// ---------------------------------------------------------------------------
extern "C" void kernel_launch(void* const* d_in, const int* in_sizes, int n_in,
                              void* d_out, int out_size)
{
    const float* Q    = (const float*)d_in[0];
    const float* K    = (const float*)d_in[1];
    const int*   mask = (const int*)d_in[3];
    const float* W    = (const float*)d_in[4];
    const float* bc   = (const float*)d_in[5];
    const float* wl   = (const float*)d_in[6];
    float*       out  = (float*)d_out;

    proj_kernel<<<(2 * PBH * PLQ) / 64, 256>>>(Q, K, W, bc);
    attn_kernel<<<PBH * (PLQ / TQ), 128>>>(mask, wl, out);
}